// round 7
// baseline (speedup 1.0000x reference)
#include <cuda_runtime.h>
#include <cuda_bf16.h>
#include <math.h>
#include <stdint.h>

// ---------------- problem constants ----------------
#define BB    16
#define CCH   256
#define HH    56
#define WW    56
#define HWSZ  (HH*WW)            // 3136
#define PIX   (BB*HWSZ)          // 50176
#define HEADS 8
#define DHEAD 32
#define BLOCK 7
#define HALO  3
#define WIN   13
#define NWIN  1024
#define HIDDEN 1024

// ---------------- scratch (device globals) ----------------
__device__ float          g_xn  [(size_t)PIX*256];
__device__ __nv_bfloat16  g_xln [(size_t)PIX*256];
__device__ __nv_bfloat16  g_qkvb[(size_t)PIX*768];
__device__ __nv_bfloat16  g_attn[(size_t)PIX*256];
__device__ float          g_x1  [(size_t)PIX*256];
__device__ __nv_bfloat16  g_x2  [(size_t)PIX*256];
__device__ __nv_bfloat16  g_h   [(size_t)PIX*1024];
__device__ __nv_bfloat16  g_wqkv[768*256];
__device__ __nv_bfloat16  g_wo  [256*256];
__device__ __nv_bfloat16  g_fc1 [1024*256];
__device__ __nv_bfloat16  g_fc2 [256*1024];
__device__ __nv_bfloat16  g_koh [176*32];     // K' one-hot extension (all CTAs share)

// ---------------- helpers ----------------
__device__ __forceinline__ uint32_t s2u(const void* p) {
    return (uint32_t)__cvta_generic_to_shared(p);
}
#define SWZ(x) ((x) ^ (((x) >> 3) & 0x70))

__device__ __forceinline__ unsigned pack_bf2(float a, float b) {
    __nv_bfloat162 t = __floats2bfloat162_rn(a, b);
    return *reinterpret_cast<unsigned*>(&t);
}

#define CPA(dst, src) \
    asm volatile("cp.async.cg.shared.global [%0], [%1], 16;" \
                 :: "r"(dst), "l"(src) : "memory")

__device__ __forceinline__ void ldm4(uint32_t* r, uint32_t addr) {
    asm volatile("ldmatrix.sync.aligned.m8n8.x4.shared.b16 {%0,%1,%2,%3}, [%4];"
        : "=r"(r[0]), "=r"(r[1]), "=r"(r[2]), "=r"(r[3]) : "r"(addr));
}
__device__ __forceinline__ void ldm4t(uint32_t* r, uint32_t addr) {
    asm volatile("ldmatrix.sync.aligned.m8n8.x4.trans.shared.b16 {%0,%1,%2,%3}, [%4];"
        : "=r"(r[0]), "=r"(r[1]), "=r"(r[2]), "=r"(r[3]) : "r"(addr));
}
__device__ __forceinline__ void mma16816(float* c, const uint32_t* a,
                                         const uint32_t* b) {
    asm volatile(
        "mma.sync.aligned.m16n8k16.row.col.f32.bf16.bf16.f32 "
        "{%0,%1,%2,%3}, {%4,%5,%6,%7}, {%8,%9}, {%0,%1,%2,%3};"
        : "+f"(c[0]), "+f"(c[1]), "+f"(c[2]), "+f"(c[3])
        : "r"(a[0]), "r"(a[1]), "r"(a[2]), "r"(a[3]), "r"(b[0]), "r"(b[1]));
}

// ---------------- weight conversion + one-hot table ----------------
__global__ void prep_w(const float* __restrict__ wq, const float* __restrict__ wkv,
                       const float* __restrict__ wo, const float* __restrict__ fc1w,
                       const float* __restrict__ fc2w)
{
    int i = blockIdx.x * 256 + threadIdx.x;      // 0..262143
    if (i < 65536) {
        g_wqkv[i] = __float2bfloat16(wq[i] * 0.17677669529663687f);
        g_wo[i]   = __float2bfloat16(wo[i]);
    }
    if (i < 131072) g_wqkv[65536 + i] = __float2bfloat16(wkv[i]);
    g_fc1[i] = __float2bfloat16(fc1w[i]);
    g_fc2[i] = __float2bfloat16(fc2w[i]);
    if (i < 5632) {                               // K' one-hots: 176 x 32
        int j = i >> 5, d = i & 31;
        int ki = (j * 1261) >> 14, kj = j - 13*ki;
        float v = ((d == ki) || (d == 14 + kj)) ? 1.f : 0.f;
        g_koh[i] = __float2bfloat16(v);
    }
}

// ---------------- LN1: NCHW -> NHWC (bf16 ln output + fp32 raw copy) ----------------
__global__ void __launch_bounds__(256)
ln1_kernel(const float* __restrict__ x, const float* __restrict__ w,
           const float* __restrict__ bch)
{
    __shared__ float sm[256][33];
    __shared__ float smu[32], srs[32];
    const int t = threadIdx.x;
    const int pixbase = blockIdx.x * 32;
    const int b   = pixbase / HWSZ;
    const int hw0 = pixbase % HWSZ;
    const float* xb = x + (size_t)b*CCH*HWSZ + hw0;
    const int lane = t & 31, grp = t >> 5;

    #pragma unroll
    for (int i = 0; i < 32; i++) {
        int c = i*8 + grp;
        sm[c][lane] = xb[(size_t)c*HWSZ + lane];
    }
    __syncthreads();

    #pragma unroll
    for (int pi = 0; pi < 4; pi++) {
        int px = grp*4 + pi;
        float s = 0.f, s2 = 0.f;
        #pragma unroll
        for (int j = 0; j < 8; j++) {
            float v = sm[lane + j*32][px];
            s += v; s2 += v*v;
        }
        #pragma unroll
        for (int o = 16; o; o >>= 1) {
            s  += __shfl_xor_sync(~0u, s,  o);
            s2 += __shfl_xor_sync(~0u, s2, o);
        }
        if (lane == 0) {
            float mu = s * (1.f/256.f);
            smu[px] = mu;
            srs[px] = rsqrtf(s2*(1.f/256.f) - mu*mu + 1e-6f);
        }
    }
    __syncthreads();

    const float wgt = w[t], bia = bch[t];
    #pragma unroll
    for (int i = 0; i < 32; i++) {
        float v = sm[t][i];
        size_t row = (size_t)(pixbase + i) * 256;
        g_xn [row + t] = v;
        g_xln[row + t] = __float2bfloat16((v - smu[i]) * srs[i] * wgt + bia);
    }
}

// ---------------- LN2: NHWC rows, fp32 in -> bf16 out ----------------
__global__ void __launch_bounds__(256)
ln2_kernel(const float* __restrict__ x1, const float* __restrict__ w,
           const float* __restrict__ bch, __nv_bfloat16* __restrict__ x2)
{
    int gw = (blockIdx.x * blockDim.x + threadIdx.x) >> 5;
    int lane = threadIdx.x & 31;
    if (gw >= PIX) return;
    const float4* r = (const float4*)(x1 + (size_t)gw*256);
    float4 a = r[lane], c = r[lane + 32];
    float s  = a.x+a.y+a.z+a.w + c.x+c.y+c.z+c.w;
    float s2 = a.x*a.x+a.y*a.y+a.z*a.z+a.w*a.w
             + c.x*c.x+c.y*c.y+c.z*c.z+c.w*c.w;
    #pragma unroll
    for (int o = 16; o; o >>= 1) {
        s  += __shfl_xor_sync(~0u, s,  o);
        s2 += __shfl_xor_sync(~0u, s2, o);
    }
    float mu   = s * (1.f/256.f);
    float rstd = rsqrtf(s2*(1.f/256.f) - mu*mu + 1e-6f);
    const float4* w4 = (const float4*)w;
    const float4* b4 = (const float4*)bch;
    float4 wa = w4[lane], ba = b4[lane];
    float4 wc = w4[lane+32], bc = b4[lane+32];
    uint2* o2 = (uint2*)(x2 + (size_t)gw*256);
    uint2 ua, uc;
    ua.x = pack_bf2((a.x-mu)*rstd*wa.x + ba.x, (a.y-mu)*rstd*wa.y + ba.y);
    ua.y = pack_bf2((a.z-mu)*rstd*wa.z + ba.z, (a.w-mu)*rstd*wa.w + ba.w);
    uc.x = pack_bf2((c.x-mu)*rstd*wc.x + bc.x, (c.y-mu)*rstd*wc.y + bc.y);
    uc.y = pack_bf2((c.z-mu)*rstd*wc.z + bc.z, (c.w-mu)*rstd*wc.w + bc.w);
    o2[lane] = ua;
    o2[lane + 32] = uc;
}

// ---------------- MMA halo attention, bias folded into extended-K MMA -----------
// Q'[qi] = [q(32) | qh(14) | qw(13) | 0(5)]  (bias bf16; -3.39e38 = masked)
// K'[j]  = [k(32) | onehot(ki) (14) | onehot(kj) (13) | 0(5)]  (from g_koh, L2-hot)
// Q rows 49->64, keys 169->176 (ki=13 slot masks padded j). Row stride 144B.
// Apply stage + max-pass eliminated; softmax straight on accumulators.
#define Q_OFF   0
#define K_OFF   9216
#define V_OFF   34560
#define SRH_OFF 48640
#define SRW_OFF 51940
#define JB_OFF  55240
#define SMEM_ATTN 55944
__global__ void __launch_bounds__(128)
halo_attn_mma(const float* __restrict__ relh, const float* __restrict__ relw,
              const __nv_bfloat16* __restrict__ qkv, __nv_bfloat16* __restrict__ attn)
{
    extern __shared__ char sm[];
    const uint32_t smu = s2u(sm);
    float* srh   = (float*)(sm + SRH_OFF);  // 25 x 33
    float* srw   = (float*)(sm + SRW_OFF);  // 25 x 33
    int*   jbase = (int*)  (sm + JB_OFF);   // 176

    const int tid  = threadIdx.x;
    const int head = blockIdx.x & 7;
    const int win  = blockIdx.x >> 3;
    const int b    = win >> 6, blk = win & 63;
    const int rowbase = (blk >> 3) * BLOCK, colbase = (blk & 7) * BLOCK;
    const int pb = b * HWSZ;
    const int hc = head * DHEAD;

    // ---- phase 0: rel tables, jbase, Q data + Q' bias defaults ----
    for (int i = tid; i < 800; i += 128) {
        int r = i >> 5, d = i & 31;
        srh[r*33 + d] = relh[i];
        srw[r*33 + d] = relw[i];
    }
    for (int j = tid; j < 176; j += 128) {
        int ki = (j * 1261) >> 14, kj = j - 13*ki;
        int gr = rowbase + ki - HALO, gc = colbase + kj - HALO;
        bool ok = (j < 169) && gr >= 0 && gr < HH && gc >= 0 && gc < WW;
        jbase[j] = ok ? ((pb + gr*WW + gc)*768 + hc) : -1;
    }
    for (int i = tid; i < 512; i += 128) {          // Q: 64 rows x 8 uint4
        int qi = i >> 3, seg = i & 7;
        if (seg < 4) {                              // data dims 0..31
            uint4 v = make_uint4(0, 0, 0, 0);
            if (qi < 49) {
                int x = qi / 7, y = qi - 7*x;
                int p = pb + (rowbase + x)*WW + colbase + y;
                v = *(const uint4*)(qkv + (size_t)p*768 + hc + seg*8);
            }
            *(uint4*)(sm + Q_OFF + qi*144 + seg*16) = v;
        } else {                                    // bias dims 32..63 default
            *(uint4*)(sm + Q_OFF + qi*144 + seg*16) =
                make_uint4(0xFF7FFF7Fu, 0xFF7FFF7Fu, 0xFF7FFF7Fu, 0xFF7FFF7Fu);
        }
    }
    __syncthreads();

    // ---- phase 1: K/V data fill + K' one-hots + Q' bias values ----
    for (int i = tid; i < 704; i += 128) {          // K,V data: 176 rows x 4 uint4
        int j = i >> 2, seg = i & 3;
        int base = jbase[j];
        uint4 kv = make_uint4(0, 0, 0, 0), vv = make_uint4(0, 0, 0, 0);
        if (base >= 0) {
            kv = *(const uint4*)(qkv + base + 256 + seg*8);
            vv = *(const uint4*)(qkv + base + 512 + seg*8);
        }
        *(uint4*)(sm + K_OFF + j*144 + seg*16) = kv;
        *(uint4*)(sm + V_OFF + j*80  + seg*16) = vv;
    }
    for (int i = tid; i < 704; i += 128) {          // K' one-hots from global const
        int j = i >> 2, seg = i & 3;
        *(uint4*)(sm + K_OFF + j*144 + 64 + seg*16) =
            ((const uint4*)g_koh)[j*4 + seg];
    }
    for (int e = tid; e < 49*14; e += 128) {        // Q' dims 32..45: qh
        int qi = e / 14, r = e % 14;
        int x = qi / 7;
        int gr = rowbase + r - HALO;
        if (r < 13 && gr >= 0 && gr < HH) {
            const uint32_t* q = (const uint32_t*)(sm + Q_OFF + qi*144);
            const float* rl = srh + (r + 12 - x)*33;
            float acc = 0.f;
            #pragma unroll
            for (int d2 = 0; d2 < 16; d2++) {
                __nv_bfloat162 qq = *(const __nv_bfloat162*)&q[d2];
                acc += __bfloat162float(qq.x)*rl[d2*2] +
                       __bfloat162float(qq.y)*rl[d2*2+1];
            }
            *(__nv_bfloat16*)(sm + Q_OFF + qi*144 + (32 + r)*2) = __float2bfloat16(acc);
        }
    }
    for (int e = tid; e < 49*13; e += 128) {        // Q' dims 46..58: qw
        int qi = e / 13, r = e % 13;
        int y = qi % 7;
        int gc = colbase + r - HALO;
        if (gc >= 0 && gc < WW) {
            const uint32_t* q = (const uint32_t*)(sm + Q_OFF + qi*144);
            const float* rl = srw + (r + 12 - y)*33;
            float acc = 0.f;
            #pragma unroll
            for (int d2 = 0; d2 < 16; d2++) {
                __nv_bfloat162 qq = *(const __nv_bfloat162*)&q[d2];
                acc += __bfloat162float(qq.x)*rl[d2*2] +
                       __bfloat162float(qq.y)*rl[d2*2+1];
            }
            *(__nv_bfloat16*)(sm + Q_OFF + qi*144 + (46 + r)*2) = __float2bfloat16(acc);
        }
    }
    __syncthreads();

    const int lane = tid & 31, wm = tid >> 5;

    // ---- Q'K'^T: 64x176x64, warp wm owns rows wm*16..+15 ----
    float c[22][4];
    #pragma unroll
    for (int nt = 0; nt < 22; nt++)
        #pragma unroll
        for (int e = 0; e < 4; e++) c[nt][e] = 0.f;

    const uint32_t a_addr  = smu + Q_OFF + (wm*16 + (lane & 15))*144 + (lane >> 4)*16;
    const uint32_t b_row   = (lane & 7) + ((lane & 16) >> 1);
    const uint32_t b_col16 = ((lane >> 3) & 1) * 16;
    #pragma unroll
    for (int kt = 0; kt < 4; kt++) {
        uint32_t a[4];
        ldm4(a, a_addr + kt*32);
        #pragma unroll
        for (int nt2 = 0; nt2 < 11; nt2++) {
            uint32_t bfr[4];
            ldm4(bfr, smu + K_OFF + (nt2*16 + b_row)*144 + kt*32 + b_col16);
            mma16816(c[2*nt2],     a, bfr);
            mma16816(c[2*nt2 + 1], a, bfr + 2);
        }
    }

    // ---- softmax (bias & mask already in logits; logits tiny -> no max pass) ----
    float sA = 0.f, sB = 0.f;
    #pragma unroll
    for (int nt = 0; nt < 22; nt++) {
        c[nt][0] = __expf(c[nt][0]); sA += c[nt][0];
        c[nt][1] = __expf(c[nt][1]); sA += c[nt][1];
        c[nt][2] = __expf(c[nt][2]); sB += c[nt][2];
        c[nt][3] = __expf(c[nt][3]); sB += c[nt][3];
    }
    sA += __shfl_xor_sync(~0u, sA, 1); sA += __shfl_xor_sync(~0u, sA, 2);
    sB += __shfl_xor_sync(~0u, sB, 1); sB += __shfl_xor_sync(~0u, sB, 2);
    const float invA = 1.f / sA, invB = 1.f / sB;

    // ---- P @ V: 64x32, K-dim 176 (P repacked C-frag -> A-frag, no smem) ----
    float o[4][4];
    #pragma unroll
    for (int nt = 0; nt < 4; nt++)
        #pragma unroll
        for (int e = 0; e < 4; e++) o[nt][e] = 0.f;

    const uint32_t v_rowoff = (lane & 15);
    const uint32_t v_coloff = ((lane >> 4) * 8) * 2;
    #pragma unroll
    for (int kt2 = 0; kt2 < 11; kt2++) {
        uint32_t pa[4];
        pa[0] = pack_bf2(c[2*kt2][0],     c[2*kt2][1]);
        pa[1] = pack_bf2(c[2*kt2][2],     c[2*kt2][3]);
        pa[2] = pack_bf2(c[2*kt2 + 1][0], c[2*kt2 + 1][1]);
        pa[3] = pack_bf2(c[2*kt2 + 1][2], c[2*kt2 + 1][3]);
        const uint32_t vbase = smu + V_OFF + (kt2*16 + v_rowoff)*80 + v_coloff;
        uint32_t vb[4];
        ldm4t(vb, vbase);
        mma16816(o[0], pa, vb);
        mma16816(o[1], pa, vb + 2);
        ldm4t(vb, vbase + 32);
        mma16816(o[2], pa, vb);
        mma16816(o[3], pa, vb + 2);
    }

    // ---- store (only valid query rows) ----
    const int qiA = wm*16 + (lane >> 2);
    #pragma unroll
    for (int half = 0; half < 2; half++) {
        int qi = qiA + half*8;
        if (qi < 49) {
            int x = qi / 7, y = qi - 7*x;
            int p = pb + (rowbase + x)*WW + colbase + y;
            __nv_bfloat16* dst = attn + (size_t)p*256 + hc + (lane & 3)*2;
            float inv = half ? invB : invA;
            #pragma unroll
            for (int nt = 0; nt < 4; nt++)
                *(uint32_t*)(dst + nt*8) =
                    pack_bf2(o[nt][half*2] * inv, o[nt][half*2 + 1] * inv);
        }
    }
}

// ---------------- bf16 mma.sync GEMM: C[M,N] = A[M,K] * W[N,K]^T ----------------
// MODE 0: fp32 store   MODE 1: x1 = resid + gamma*(acc+bias) fp32
// MODE 2: bf16 gelu    MODE 3: out_nchw = resid + gamma*(acc+bias)
// MODE 4: bf16 plain store
template<int MODE>
__global__ void __launch_bounds__(256)
mgemm(const __nv_bfloat16* __restrict__ A, const __nv_bfloat16* __restrict__ W,
      float* __restrict__ Cf, __nv_bfloat16* __restrict__ Cb, int N, int K,
      const float* __restrict__ bias, const float* __restrict__ resid,
      const float* __restrict__ gamma, float* __restrict__ out2)
{
    extern __shared__ char smraw[];
    uint32_t dynb  = s2u(smraw);
    const uint32_t tiles_u = (dynb + 1023) & ~1023u;

    const int tid  = threadIdx.x;
    const int lane = tid & 31, warp = tid >> 5;
    const int wm = warp & 3, wn = warp >> 2;
    const int mBase = blockIdx.y * 128;
    const int nBase = blockIdx.x * 128;
    const __nv_bfloat16* Abase = A + (size_t)mBase * K;
    const __nv_bfloat16* Wbase = W + (size_t)nBase * K;
    const int nkt = K >> 6;

    float c[2][8][4];
    #pragma unroll
    for (int mi = 0; mi < 2; mi++)
        #pragma unroll
        for (int ni = 0; ni < 8; ni++)
            #pragma unroll
            for (int j = 0; j < 4; j++) c[mi][ni][j] = 0.f;

    const int arow0    = wm*32 + (lane & 15);
    const int acolbase = (lane >> 4) * 16;
    const int brow0    = wn*64 + ((lane >> 4) << 3) + (lane & 7);
    const int bcolbase = ((lane >> 3) & 1) * 16;

    auto LOADT = [&](int kt) {
        const __nv_bfloat16* Ag = Abase + kt * 64;
        const __nv_bfloat16* Wg = Wbase + kt * 64;
        uint32_t sa = tiles_u + (kt & 1) * 32768;
        #pragma unroll
        for (int i = 0; i < 4; i++) {
            int idx = tid + i * 256;
            int row = idx >> 3, ch = idx & 7;
            uint32_t off = SWZ(row * 128 + ch * 16);
            CPA(sa + off,         Ag + (size_t)row * K + ch * 8);
            CPA(sa + 16384 + off, Wg + (size_t)row * K + ch * 8);
        }
        asm volatile("cp.async.commit_group;" ::: "memory");
    };

    LOADT(0);
    for (int kt = 0; kt < nkt; kt++) {
        if (kt + 1 < nkt) {
            LOADT(kt + 1);
            asm volatile("cp.async.wait_group 1;" ::: "memory");
        } else {
            asm volatile("cp.async.wait_group 0;" ::: "memory");
        }
        __syncthreads();

        const uint32_t sa = tiles_u + (kt & 1) * 32768;
        const uint32_t sb = sa + 16384;
        #pragma unroll
        for (int kk = 0; kk < 4; kk++) {
            uint32_t af[2][4];
            ldm4(af[0], sa + SWZ(arow0 * 128 + kk*32 + acolbase));
            ldm4(af[1], sa + SWZ((arow0 + 16) * 128 + kk*32 + acolbase));
            uint32_t bf_[4][4];
            #pragma unroll
            for (int nj = 0; nj < 4; nj++)
                ldm4(bf_[nj], sb + SWZ((brow0 + nj*16) * 128 + kk*32 + bcolbase));
            #pragma unroll
            for (int mi = 0; mi < 2; mi++)
                #pragma unroll
                for (int ni = 0; ni < 8; ni++)
                    mma16816(c[mi][ni], af[mi], &bf_[ni >> 1][(ni & 1) * 2]);
        }
        __syncthreads();
    }

    // ---------------- epilogue ----------------
    const int colq = (lane & 3) * 2;
    const int rowq = lane >> 2;

    #pragma unroll
    for (int ni = 0; ni < 8; ni++) {
        const int col = nBase + wn*64 + ni*8 + colq;
        float2 bb = make_float2(0.f, 0.f), gg = make_float2(0.f, 0.f);
        if (MODE == 1 || MODE == 2 || MODE == 3) bb = *(const float2*)(bias + col);
        if (MODE == 1 || MODE == 3) gg = *(const float2*)(gamma + col);
        #pragma unroll
        for (int mi = 0; mi < 2; mi++) {
            #pragma unroll
            for (int h = 0; h < 2; h++) {
                const int row = mBase + wm*32 + mi*16 + h*8 + rowq;
                const float v0 = c[mi][ni][h*2], v1 = c[mi][ni][h*2+1];
                if (MODE == 0) {
                    *(float2*)(Cf + (size_t)row * N + col) = make_float2(v0, v1);
                } else if (MODE == 1) {
                    float2 r2 = *(const float2*)(resid + (size_t)row * 256 + col);
                    *(float2*)(Cf + (size_t)row * 256 + col) =
                        make_float2(r2.x + gg.x * (v0 + bb.x),
                                    r2.y + gg.y * (v1 + bb.y));
                } else if (MODE == 2) {
                    float t0 = v0 + bb.x, t1 = v1 + bb.y;
                    float e0 = 0.5f * t0 * (1.f + erff(t0 * 0.70710678118654752f));
                    float e1 = 0.5f * t1 * (1.f + erff(t1 * 0.70710678118654752f));
                    *(unsigned*)(Cb + (size_t)row * N + col) = pack_bf2(e0, e1);
                } else if (MODE == 3) {
                    const int bimg = row / HWSZ;
                    const int hw   = row - bimg * HWSZ;
                    const float* rp = resid + (size_t)row * 256 + col;
                    float* ob = out2 + (size_t)(bimg * 256 + col) * HWSZ + hw;
                    ob[0]    = rp[0] + gg.x * (v0 + bb.x);
                    ob[HWSZ] = rp[1] + gg.y * (v1 + bb.y);
                } else {
                    *(unsigned*)(Cb + (size_t)row * N + col) = pack_bf2(v0, v1);
                }
            }
        }
    }
}

// ---------------- launcher ----------------
extern "C" void kernel_launch(void* const* d_in, const int* in_sizes, int n_in,
                              void* d_out, int out_size)
{
    const float* x      = (const float*)d_in[0];
    const float* ln1w   = (const float*)d_in[1];
    const float* ln1b   = (const float*)d_in[2];
    const float* ln2w   = (const float*)d_in[3];
    const float* ln2b   = (const float*)d_in[4];
    const float* wq     = (const float*)d_in[5];
    const float* wkv    = (const float*)d_in[6];
    const float* wo     = (const float*)d_in[7];
    const float* bo     = (const float*)d_in[8];
    const float* relh   = (const float*)d_in[9];
    const float* relw   = (const float*)d_in[10];
    const float* gamma1 = (const float*)d_in[11];
    const float* gamma2 = (const float*)d_in[12];
    const float* fc1w   = (const float*)d_in[13];
    const float* fc1b   = (const float*)d_in[14];
    const float* fc2w   = (const float*)d_in[15];
    const float* fc2b   = (const float*)d_in[16];
    float* out = (float*)d_out;

    float *p_xn, *p_x1;
    __nv_bfloat16 *p_xln, *p_qkvb, *p_attn, *p_x2, *p_h, *p_wqkv, *p_wo, *p_fc1, *p_fc2;
    cudaGetSymbolAddress((void**)&p_xn,   g_xn);
    cudaGetSymbolAddress((void**)&p_xln,  g_xln);
    cudaGetSymbolAddress((void**)&p_qkvb, g_qkvb);
    cudaGetSymbolAddress((void**)&p_attn, g_attn);
    cudaGetSymbolAddress((void**)&p_x1,   g_x1);
    cudaGetSymbolAddress((void**)&p_x2,   g_x2);
    cudaGetSymbolAddress((void**)&p_h,    g_h);
    cudaGetSymbolAddress((void**)&p_wqkv, g_wqkv);
    cudaGetSymbolAddress((void**)&p_wo,   g_wo);
    cudaGetSymbolAddress((void**)&p_fc1,  g_fc1);
    cudaGetSymbolAddress((void**)&p_fc2,  g_fc2);

    cudaFuncSetAttribute(halo_attn_mma,
                         cudaFuncAttributeMaxDynamicSharedMemorySize, SMEM_ATTN);
    cudaFuncSetAttribute(mgemm<1>, cudaFuncAttributeMaxDynamicSharedMemorySize, 66560);
    cudaFuncSetAttribute(mgemm<2>, cudaFuncAttributeMaxDynamicSharedMemorySize, 66560);
    cudaFuncSetAttribute(mgemm<3>, cudaFuncAttributeMaxDynamicSharedMemorySize, 66560);
    cudaFuncSetAttribute(mgemm<4>, cudaFuncAttributeMaxDynamicSharedMemorySize, 66560);

    // 1) weights -> bf16 (q scale folded) + one-hot table
    prep_w<<<1024, 256>>>(wq, wkv, wo, fc1w, fc2w);
    // 2) LN1 + NHWC transpose (bf16 ln out + fp32 raw copy)
    ln1_kernel<<<PIX/32, 256>>>(x, ln1w, ln1b);
    // 3) QKV: (50176,256)x(768,256)^T -> bf16
    mgemm<4><<<dim3(6, 392), 256, 66560>>>(p_xln, p_wqkv, nullptr, p_qkvb, 768, 256,
                                           nullptr, nullptr, nullptr, nullptr);
    // 4) MMA halo attention (bias-in-MMA via precomputed one-hots) -> bf16
    halo_attn_mma<<<NWIN*HEADS, 128, SMEM_ATTN>>>(relh, relw, p_qkvb, p_attn);
    // 5) out proj + residual: x1 = x + gamma1*(attn@wo^T + bo)
    mgemm<1><<<dim3(2, 392), 256, 66560>>>(p_attn, p_wo, p_x1, nullptr, 256, 256,
                                           bo, p_xn, gamma1, nullptr);
    // 6) LN2 -> bf16
    ln2_kernel<<<PIX/8, 256>>>(p_x1, ln2w, ln2b, p_x2);
    // 7) fc1 + gelu -> bf16
    mgemm<2><<<dim3(8, 392), 256, 66560>>>(p_x2, p_fc1, nullptr, p_h, 1024, 256,
                                           fc1b, nullptr, nullptr, nullptr);
    // 8) fc2 + gamma2 residual + NHWC->NCHW into d_out
    mgemm<3><<<dim3(2, 392), 256, 66560>>>(p_h, p_fc2, nullptr, nullptr, 256, 1024,
                                           fc2b, p_x1, gamma2, out);
}

// round 8
// speedup vs baseline: 1.0457x; 1.0457x over previous
#include <cuda_runtime.h>
#include <cuda_bf16.h>
#include <math.h>
#include <stdint.h>

// ---------------- problem constants ----------------
#define BB    16
#define CCH   256
#define HH    56
#define WW    56
#define HWSZ  (HH*WW)            // 3136
#define PIX   (BB*HWSZ)          // 50176
#define HEADS 8
#define DHEAD 32
#define BLOCK 7
#define HALO  3
#define WIN   13
#define NWIN  1024
#define HIDDEN 1024

// ---------------- scratch (device globals) ----------------
__device__ float          g_xn  [(size_t)PIX*256];
__device__ __nv_bfloat16  g_xln [(size_t)PIX*256];
__device__ __nv_bfloat16  g_qkvb[(size_t)PIX*768];
__device__ __nv_bfloat16  g_attn[(size_t)PIX*256];
__device__ float          g_x1  [(size_t)PIX*256];
__device__ __nv_bfloat16  g_x2  [(size_t)PIX*256];
__device__ __nv_bfloat16  g_h   [(size_t)PIX*1024];
__device__ __nv_bfloat16  g_wqkv[768*256];
__device__ __nv_bfloat16  g_wo  [256*256];
__device__ __nv_bfloat16  g_fc1 [1024*256];
__device__ __nv_bfloat16  g_fc2 [256*1024];

// ---------------- helpers ----------------
__device__ __forceinline__ uint32_t s2u(const void* p) {
    return (uint32_t)__cvta_generic_to_shared(p);
}
#define SWZ(x) ((x) ^ (((x) >> 3) & 0x70))

__device__ __forceinline__ unsigned pack_bf2(float a, float b) {
    __nv_bfloat162 t = __floats2bfloat162_rn(a, b);
    return *reinterpret_cast<unsigned*>(&t);
}

#define CPA(dst, src) \
    asm volatile("cp.async.cg.shared.global [%0], [%1], 16;" \
                 :: "r"(dst), "l"(src) : "memory")

__device__ __forceinline__ void ldm4(uint32_t* r, uint32_t addr) {
    asm volatile("ldmatrix.sync.aligned.m8n8.x4.shared.b16 {%0,%1,%2,%3}, [%4];"
        : "=r"(r[0]), "=r"(r[1]), "=r"(r[2]), "=r"(r[3]) : "r"(addr));
}
__device__ __forceinline__ void ldm4t(uint32_t* r, uint32_t addr) {
    asm volatile("ldmatrix.sync.aligned.m8n8.x4.trans.shared.b16 {%0,%1,%2,%3}, [%4];"
        : "=r"(r[0]), "=r"(r[1]), "=r"(r[2]), "=r"(r[3]) : "r"(addr));
}
__device__ __forceinline__ void mma16816(float* c, const uint32_t* a,
                                         const uint32_t* b) {
    asm volatile(
        "mma.sync.aligned.m16n8k16.row.col.f32.bf16.bf16.f32 "
        "{%0,%1,%2,%3}, {%4,%5,%6,%7}, {%8,%9}, {%0,%1,%2,%3};"
        : "+f"(c[0]), "+f"(c[1]), "+f"(c[2]), "+f"(c[3])
        : "r"(a[0]), "r"(a[1]), "r"(a[2]), "r"(a[3]), "r"(b[0]), "r"(b[1]));
}

// ---------------- weight conversion to bf16 (q scale folded into wq) ----------------
__global__ void prep_w(const float* __restrict__ wq, const float* __restrict__ wkv,
                       const float* __restrict__ wo, const float* __restrict__ fc1w,
                       const float* __restrict__ fc2w)
{
    int i = blockIdx.x * 256 + threadIdx.x;      // 0..262143
    if (i < 65536) {
        g_wqkv[i] = __float2bfloat16(wq[i] * 0.17677669529663687f);
        g_wo[i]   = __float2bfloat16(wo[i]);
    }
    if (i < 131072) g_wqkv[65536 + i] = __float2bfloat16(wkv[i]);
    g_fc1[i] = __float2bfloat16(fc1w[i]);
    g_fc2[i] = __float2bfloat16(fc2w[i]);
}

// ---------------- LN1: NCHW -> NHWC (bf16 ln output + fp32 raw copy) ----------------
__global__ void __launch_bounds__(256)
ln1_kernel(const float* __restrict__ x, const float* __restrict__ w,
           const float* __restrict__ bch)
{
    __shared__ float sm[256][33];
    __shared__ float smu[32], srs[32];
    const int t = threadIdx.x;
    const int pixbase = blockIdx.x * 32;
    const int b   = pixbase / HWSZ;
    const int hw0 = pixbase % HWSZ;
    const float* xb = x + (size_t)b*CCH*HWSZ + hw0;
    const int lane = t & 31, grp = t >> 5;

    #pragma unroll
    for (int i = 0; i < 32; i++) {
        int c = i*8 + grp;
        sm[c][lane] = xb[(size_t)c*HWSZ + lane];
    }
    __syncthreads();

    #pragma unroll
    for (int pi = 0; pi < 4; pi++) {
        int px = grp*4 + pi;
        float s = 0.f, s2 = 0.f;
        #pragma unroll
        for (int j = 0; j < 8; j++) {
            float v = sm[lane + j*32][px];
            s += v; s2 += v*v;
        }
        #pragma unroll
        for (int o = 16; o; o >>= 1) {
            s  += __shfl_xor_sync(~0u, s,  o);
            s2 += __shfl_xor_sync(~0u, s2, o);
        }
        if (lane == 0) {
            float mu = s * (1.f/256.f);
            smu[px] = mu;
            srs[px] = rsqrtf(s2*(1.f/256.f) - mu*mu + 1e-6f);
        }
    }
    __syncthreads();

    const float wgt = w[t], bia = bch[t];
    #pragma unroll
    for (int i = 0; i < 32; i++) {
        float v = sm[t][i];
        size_t row = (size_t)(pixbase + i) * 256;
        g_xn [row + t] = v;
        g_xln[row + t] = __float2bfloat16((v - smu[i]) * srs[i] * wgt + bia);
    }
}

// ---------------- LN2: NHWC rows, fp32 in -> bf16 out ----------------
__global__ void __launch_bounds__(256)
ln2_kernel(const float* __restrict__ x1, const float* __restrict__ w,
           const float* __restrict__ bch, __nv_bfloat16* __restrict__ x2)
{
    int gw = (blockIdx.x * blockDim.x + threadIdx.x) >> 5;
    int lane = threadIdx.x & 31;
    if (gw >= PIX) return;
    const float4* r = (const float4*)(x1 + (size_t)gw*256);
    float4 a = r[lane], c = r[lane + 32];
    float s  = a.x+a.y+a.z+a.w + c.x+c.y+c.z+c.w;
    float s2 = a.x*a.x+a.y*a.y+a.z*a.z+a.w*a.w
             + c.x*c.x+c.y*c.y+c.z*c.z+c.w*c.w;
    #pragma unroll
    for (int o = 16; o; o >>= 1) {
        s  += __shfl_xor_sync(~0u, s,  o);
        s2 += __shfl_xor_sync(~0u, s2, o);
    }
    float mu   = s * (1.f/256.f);
    float rstd = rsqrtf(s2*(1.f/256.f) - mu*mu + 1e-6f);
    const float4* w4 = (const float4*)w;
    const float4* b4 = (const float4*)bch;
    float4 wa = w4[lane], ba = b4[lane];
    float4 wc = w4[lane+32], bc = b4[lane+32];
    uint2* o2 = (uint2*)(x2 + (size_t)gw*256);
    uint2 ua, uc;
    ua.x = pack_bf2((a.x-mu)*rstd*wa.x + ba.x, (a.y-mu)*rstd*wa.y + ba.y);
    ua.y = pack_bf2((a.z-mu)*rstd*wa.z + ba.z, (a.w-mu)*rstd*wa.w + ba.w);
    uc.x = pack_bf2((c.x-mu)*rstd*wc.x + bc.x, (c.y-mu)*rstd*wc.y + bc.y);
    uc.y = pack_bf2((c.z-mu)*rstd*wc.z + bc.z, (c.w-mu)*rstd*wc.w + bc.w);
    o2[lane] = ua;
    o2[lane + 32] = uc;
}

// ---------------- MMA halo attention: one CTA (128 thr) per (window, head) ----------
// Q padded 49->64 rows, keys padded 169->176. Row stride 80B.
// uint4 vectorized fills; bias tables stride 20 words (bank-conflict-free apply).
#define Q_OFF   0
#define K_OFF   5120
#define V_OFF   19200
#define QH_OFF  33280
#define QW_OFF  38400
#define SRH_OFF 43520
#define SRW_OFF 46820
#define JB_OFF  50120
#define SMEM_ATTN 50824
__global__ void __launch_bounds__(128)
halo_attn_mma(const float* __restrict__ relh, const float* __restrict__ relw,
              const __nv_bfloat16* __restrict__ qkv, __nv_bfloat16* __restrict__ attn)
{
    extern __shared__ char sm[];
    const uint32_t smu = s2u(sm);
    float* qh2   = (float*)(sm + QH_OFF);   // 64 x 20
    float* qw2   = (float*)(sm + QW_OFF);   // 64 x 20
    float* srh   = (float*)(sm + SRH_OFF);  // 25 x 33
    float* srw   = (float*)(sm + SRW_OFF);  // 25 x 33
    int*   jbase = (int*)  (sm + JB_OFF);   // 176

    const int tid  = threadIdx.x;
    const int head = blockIdx.x & 7;
    const int win  = blockIdx.x >> 3;
    const int b    = win >> 6, blk = win & 63;
    const int rowbase = (blk >> 3) * BLOCK, colbase = (blk & 7) * BLOCK;
    const int pb = b * HWSZ;
    const int hc = head * DHEAD;

    // ---- phase 0: rel tables, jbase, Q fill (uint4), bias defaults ----
    for (int i = tid; i < 800; i += 128) {
        int r = i >> 5, d = i & 31;
        srh[r*33 + d] = relh[i];
        srw[r*33 + d] = relw[i];
    }
    for (int j = tid; j < 176; j += 128) {
        int ki = (j * 1261) >> 14, kj = j - 13*ki;
        int gr = rowbase + ki - HALO, gc = colbase + kj - HALO;
        bool ok = (j < 169) && gr >= 0 && gr < HH && gc >= 0 && gc < WW;
        jbase[j] = ok ? ((pb + gr*WW + gc)*768 + hc) : -1;
    }
    for (int i = tid; i < 256; i += 128) {          // Q: 64 rows x 4 uint4
        int qi = i >> 2, seg = i & 3;
        uint4 v = make_uint4(0, 0, 0, 0);
        if (qi < 49) {
            int x = qi / 7, y = qi - 7*x;
            int p = pb + (rowbase + x)*WW + colbase + y;
            v = *(const uint4*)(qkv + (size_t)p*768 + hc + seg*8);
        }
        *(uint4*)(sm + Q_OFF + qi*80 + seg*16) = v;
    }
    for (int i = tid; i < 640; i += 128) {          // qh2/qw2 default -3.4e38
        ((uint4*)(sm + QH_OFF))[i] =
            make_uint4(0xFF7FFFFFu, 0xFF7FFFFFu, 0xFF7FFFFFu, 0xFF7FFFFFu);
    }
    __syncthreads();

    // ---- phase 1: K/V fill (uint4, via jbase) + bias tables ----
    for (int i = tid; i < 704; i += 128) {          // 176 rows x 4 uint4
        int j = i >> 2, seg = i & 3;
        int base = jbase[j];
        uint4 kv = make_uint4(0, 0, 0, 0), vv = make_uint4(0, 0, 0, 0);
        if (base >= 0) {
            kv = *(const uint4*)(qkv + base + 256 + seg*8);
            vv = *(const uint4*)(qkv + base + 512 + seg*8);
        }
        *(uint4*)(sm + K_OFF + j*80 + seg*16) = kv;
        *(uint4*)(sm + V_OFF + j*80 + seg*16) = vv;
    }
    for (int e = tid; e < 49*14; e += 128) {        // qh2[qi][ki]
        int qi = e / 14, r = e % 14;
        int x = qi / 7;
        int gr = rowbase + r - HALO;
        if (r < 13 && gr >= 0 && gr < HH) {
            const uint32_t* q = (const uint32_t*)(sm + Q_OFF + qi*80);
            const float* rl = srh + (r + 12 - x)*33;
            float acc = 0.f;
            #pragma unroll
            for (int d2 = 0; d2 < 16; d2++) {
                __nv_bfloat162 qq = *(const __nv_bfloat162*)&q[d2];
                acc += __bfloat162float(qq.x)*rl[d2*2] +
                       __bfloat162float(qq.y)*rl[d2*2+1];
            }
            qh2[qi*20 + r] = acc;
        }
    }
    for (int e = tid; e < 49*13; e += 128) {        // qw2[qi][kj]
        int qi = e / 13, r = e % 13;
        int y = qi % 7;
        int gc = colbase + r - HALO;
        if (gc >= 0 && gc < WW) {
            const uint32_t* q = (const uint32_t*)(sm + Q_OFF + qi*80);
            const float* rl = srw + (r + 12 - y)*33;
            float acc = 0.f;
            #pragma unroll
            for (int d2 = 0; d2 < 16; d2++) {
                __nv_bfloat162 qq = *(const __nv_bfloat162*)&q[d2];
                acc += __bfloat162float(qq.x)*rl[d2*2] +
                       __bfloat162float(qq.y)*rl[d2*2+1];
            }
            qw2[qi*20 + r] = acc;
        }
    }
    __syncthreads();

    const int lane = tid & 31, wm = tid >> 5;

    // ---- QK^T: 64x176x32, warp wm owns rows wm*16..+15 ----
    float c[22][4];
    #pragma unroll
    for (int nt = 0; nt < 22; nt++)
        #pragma unroll
        for (int e = 0; e < 4; e++) c[nt][e] = 0.f;

    const uint32_t a_addr  = smu + Q_OFF + (wm*16 + (lane & 15))*80 + ((lane >> 4)*8)*2;
    const uint32_t b_row   = (lane & 7) + ((lane & 16) >> 1);
    const uint32_t b_col16 = ((lane >> 3) & 1) * 16;
    #pragma unroll
    for (int kt = 0; kt < 2; kt++) {
        uint32_t a[4];
        ldm4(a, a_addr + kt*32);
        #pragma unroll
        for (int nt2 = 0; nt2 < 11; nt2++) {
            uint32_t bfr[4];
            ldm4(bfr, smu + K_OFF + (nt2*16 + b_row)*80 + kt*32 + b_col16);
            mma16816(c[2*nt2],     a, bfr);
            mma16816(c[2*nt2 + 1], a, bfr + 2);
        }
    }

    // ---- bias + mask (stride-20 tables: conflict-free) + softmax ----
    const int qiA = wm*16 + (lane >> 2);
    #pragma unroll
    for (int nt = 0; nt < 22; nt++) {
        #pragma unroll
        for (int e = 0; e < 2; e++) {
            int j  = nt*8 + (lane & 3)*2 + e;
            int ki = (j * 1261) >> 14, kj = j - 13*ki;
            c[nt][e]     += qh2[qiA*20 + ki]     + qw2[qiA*20 + kj];
            c[nt][e + 2] += qh2[(qiA+8)*20 + ki] + qw2[(qiA+8)*20 + kj];
        }
    }
    float mA = -3.4e38f, mB = -3.4e38f;
    #pragma unroll
    for (int nt = 0; nt < 22; nt++) {
        mA = fmaxf(mA, fmaxf(c[nt][0], c[nt][1]));
        mB = fmaxf(mB, fmaxf(c[nt][2], c[nt][3]));
    }
    mA = fmaxf(mA, __shfl_xor_sync(~0u, mA, 1));
    mA = fmaxf(mA, __shfl_xor_sync(~0u, mA, 2));
    mB = fmaxf(mB, __shfl_xor_sync(~0u, mB, 1));
    mB = fmaxf(mB, __shfl_xor_sync(~0u, mB, 2));
    float sA = 0.f, sB = 0.f;
    #pragma unroll
    for (int nt = 0; nt < 22; nt++) {
        c[nt][0] = __expf(c[nt][0] - mA); sA += c[nt][0];
        c[nt][1] = __expf(c[nt][1] - mA); sA += c[nt][1];
        c[nt][2] = __expf(c[nt][2] - mB); sB += c[nt][2];
        c[nt][3] = __expf(c[nt][3] - mB); sB += c[nt][3];
    }
    sA += __shfl_xor_sync(~0u, sA, 1); sA += __shfl_xor_sync(~0u, sA, 2);
    sB += __shfl_xor_sync(~0u, sB, 1); sB += __shfl_xor_sync(~0u, sB, 2);
    const float invA = 1.f / sA, invB = 1.f / sB;

    // ---- P @ V: 64x32, K-dim 176 (P repacked C-frag -> A-frag, no smem) ----
    float o[4][4];
    #pragma unroll
    for (int nt = 0; nt < 4; nt++)
        #pragma unroll
        for (int e = 0; e < 4; e++) o[nt][e] = 0.f;

    const uint32_t v_rowoff = (lane & 15);
    const uint32_t v_coloff = ((lane >> 4) * 8) * 2;
    #pragma unroll
    for (int kt2 = 0; kt2 < 11; kt2++) {
        uint32_t pa[4];
        pa[0] = pack_bf2(c[2*kt2][0],     c[2*kt2][1]);
        pa[1] = pack_bf2(c[2*kt2][2],     c[2*kt2][3]);
        pa[2] = pack_bf2(c[2*kt2 + 1][0], c[2*kt2 + 1][1]);
        pa[3] = pack_bf2(c[2*kt2 + 1][2], c[2*kt2 + 1][3]);
        const uint32_t vbase = smu + V_OFF + (kt2*16 + v_rowoff)*80 + v_coloff;
        uint32_t vb[4];
        ldm4t(vb, vbase);
        mma16816(o[0], pa, vb);
        mma16816(o[1], pa, vb + 2);
        ldm4t(vb, vbase + 32);
        mma16816(o[2], pa, vb);
        mma16816(o[3], pa, vb + 2);
    }

    // ---- store (only valid query rows) ----
    #pragma unroll
    for (int half = 0; half < 2; half++) {
        int qi = qiA + half*8;
        if (qi < 49) {
            int x = qi / 7, y = qi - 7*x;
            int p = pb + (rowbase + x)*WW + colbase + y;
            __nv_bfloat16* dst = attn + (size_t)p*256 + hc + (lane & 3)*2;
            float inv = half ? invB : invA;
            #pragma unroll
            for (int nt = 0; nt < 4; nt++)
                *(uint32_t*)(dst + nt*8) =
                    pack_bf2(o[nt][half*2] * inv, o[nt][half*2 + 1] * inv);
        }
    }
}

// ---------------- bf16 mma.sync GEMM: C[M,N] = A[M,K] * W[N,K]^T ----------------
// CTA tile 128x128, warp tile 32x64, k-tile 64, cp.async 3-stage pipeline.
// MODE 0: fp32 store   MODE 1: x1 = resid + gamma*(acc+bias) fp32
// MODE 2: bf16 gelu    MODE 3: out_nchw = resid + gamma*(acc+bias)
// MODE 4: bf16 plain store
#define GEMM_SMEM (3*32768)
template<int MODE>
__global__ void __launch_bounds__(256)
mgemm(const __nv_bfloat16* __restrict__ A, const __nv_bfloat16* __restrict__ W,
      float* __restrict__ Cf, __nv_bfloat16* __restrict__ Cb, int N, int K,
      const float* __restrict__ bias, const float* __restrict__ resid,
      const float* __restrict__ gamma, float* __restrict__ out2)
{
    extern __shared__ char smraw[];
    uint32_t dynb  = s2u(smraw);
    const uint32_t tiles_u = (dynb + 1023) & ~1023u;

    const int tid  = threadIdx.x;
    const int lane = tid & 31, warp = tid >> 5;
    const int wm = warp & 3, wn = warp >> 2;
    const int mBase = blockIdx.y * 128;
    const int nBase = blockIdx.x * 128;
    const __nv_bfloat16* Abase = A + (size_t)mBase * K;
    const __nv_bfloat16* Wbase = W + (size_t)nBase * K;
    const int nkt = K >> 6;

    float c[2][8][4];
    #pragma unroll
    for (int mi = 0; mi < 2; mi++)
        #pragma unroll
        for (int ni = 0; ni < 8; ni++)
            #pragma unroll
            for (int j = 0; j < 4; j++) c[mi][ni][j] = 0.f;

    const int arow0    = wm*32 + (lane & 15);
    const int acolbase = (lane >> 4) * 16;
    const int brow0    = wn*64 + ((lane >> 4) << 3) + (lane & 7);
    const int bcolbase = ((lane >> 3) & 1) * 16;

    // 3-stage buffers: buf kt%3, each 32KB (A 16KB | B 16KB)
    auto LOADT = [&](int kt) {
        const __nv_bfloat16* Ag = Abase + kt * 64;
        const __nv_bfloat16* Wg = Wbase + kt * 64;
        uint32_t sa = tiles_u + (kt % 3) * 32768;
        #pragma unroll
        for (int i = 0; i < 4; i++) {
            int idx = tid + i * 256;
            int row = idx >> 3, ch = idx & 7;
            uint32_t off = SWZ(row * 128 + ch * 16);
            CPA(sa + off,         Ag + (size_t)row * K + ch * 8);
            CPA(sa + 16384 + off, Wg + (size_t)row * K + ch * 8);
        }
        asm volatile("cp.async.commit_group;" ::: "memory");
    };

    LOADT(0);
    if (nkt > 1) LOADT(1);
    for (int kt = 0; kt < nkt; kt++) {
        if (kt + 1 < nkt) {
            asm volatile("cp.async.wait_group 1;" ::: "memory");
        } else {
            asm volatile("cp.async.wait_group 0;" ::: "memory");
        }
        __syncthreads();
        // safe: all warps finished compute(kt-1), whose buffer (kt-1)%3 == (kt+2)%3
        if (kt + 2 < nkt) LOADT(kt + 2);

        const uint32_t sa = tiles_u + (kt % 3) * 32768;
        const uint32_t sb = sa + 16384;
        #pragma unroll
        for (int kk = 0; kk < 4; kk++) {
            uint32_t af[2][4];
            ldm4(af[0], sa + SWZ(arow0 * 128 + kk*32 + acolbase));
            ldm4(af[1], sa + SWZ((arow0 + 16) * 128 + kk*32 + acolbase));
            uint32_t bf_[4][4];
            #pragma unroll
            for (int nj = 0; nj < 4; nj++)
                ldm4(bf_[nj], sb + SWZ((brow0 + nj*16) * 128 + kk*32 + bcolbase));
            #pragma unroll
            for (int mi = 0; mi < 2; mi++)
                #pragma unroll
                for (int ni = 0; ni < 8; ni++)
                    mma16816(c[mi][ni], af[mi], &bf_[ni >> 1][(ni & 1) * 2]);
        }
    }

    // ---------------- epilogue ----------------
    const int colq = (lane & 3) * 2;
    const int rowq = lane >> 2;

    #pragma unroll
    for (int ni = 0; ni < 8; ni++) {
        const int col = nBase + wn*64 + ni*8 + colq;
        float2 bb = make_float2(0.f, 0.f), gg = make_float2(0.f, 0.f);
        if (MODE == 1 || MODE == 2 || MODE == 3) bb = *(const float2*)(bias + col);
        if (MODE == 1 || MODE == 3) gg = *(const float2*)(gamma + col);
        #pragma unroll
        for (int mi = 0; mi < 2; mi++) {
            #pragma unroll
            for (int h = 0; h < 2; h++) {
                const int row = mBase + wm*32 + mi*16 + h*8 + rowq;
                const float v0 = c[mi][ni][h*2], v1 = c[mi][ni][h*2+1];
                if (MODE == 0) {
                    *(float2*)(Cf + (size_t)row * N + col) = make_float2(v0, v1);
                } else if (MODE == 1) {
                    float2 r2 = *(const float2*)(resid + (size_t)row * 256 + col);
                    *(float2*)(Cf + (size_t)row * 256 + col) =
                        make_float2(r2.x + gg.x * (v0 + bb.x),
                                    r2.y + gg.y * (v1 + bb.y));
                } else if (MODE == 2) {
                    float t0 = v0 + bb.x, t1 = v1 + bb.y;
                    float e0 = 0.5f * t0 * (1.f + erff(t0 * 0.70710678118654752f));
                    float e1 = 0.5f * t1 * (1.f + erff(t1 * 0.70710678118654752f));
                    *(unsigned*)(Cb + (size_t)row * N + col) = pack_bf2(e0, e1);
                } else if (MODE == 3) {
                    const int bimg = row / HWSZ;
                    const int hw   = row - bimg * HWSZ;
                    const float* rp = resid + (size_t)row * 256 + col;
                    float* ob = out2 + (size_t)(bimg * 256 + col) * HWSZ + hw;
                    ob[0]    = rp[0] + gg.x * (v0 + bb.x);
                    ob[HWSZ] = rp[1] + gg.y * (v1 + bb.y);
                } else {
                    *(unsigned*)(Cb + (size_t)row * N + col) = pack_bf2(v0, v1);
                }
            }
        }
    }
}

// ---------------- launcher ----------------
extern "C" void kernel_launch(void* const* d_in, const int* in_sizes, int n_in,
                              void* d_out, int out_size)
{
    const float* x      = (const float*)d_in[0];
    const float* ln1w   = (const float*)d_in[1];
    const float* ln1b   = (const float*)d_in[2];
    const float* ln2w   = (const float*)d_in[3];
    const float* ln2b   = (const float*)d_in[4];
    const float* wq     = (const float*)d_in[5];
    const float* wkv    = (const float*)d_in[6];
    const float* wo     = (const float*)d_in[7];
    const float* bo     = (const float*)d_in[8];
    const float* relh   = (const float*)d_in[9];
    const float* relw   = (const float*)d_in[10];
    const float* gamma1 = (const float*)d_in[11];
    const float* gamma2 = (const float*)d_in[12];
    const float* fc1w   = (const float*)d_in[13];
    const float* fc1b   = (const float*)d_in[14];
    const float* fc2w   = (const float*)d_in[15];
    const float* fc2b   = (const float*)d_in[16];
    float* out = (float*)d_out;

    float *p_xn, *p_x1;
    __nv_bfloat16 *p_xln, *p_qkvb, *p_attn, *p_x2, *p_h, *p_wqkv, *p_wo, *p_fc1, *p_fc2;
    cudaGetSymbolAddress((void**)&p_xn,   g_xn);
    cudaGetSymbolAddress((void**)&p_xln,  g_xln);
    cudaGetSymbolAddress((void**)&p_qkvb, g_qkvb);
    cudaGetSymbolAddress((void**)&p_attn, g_attn);
    cudaGetSymbolAddress((void**)&p_x1,   g_x1);
    cudaGetSymbolAddress((void**)&p_x2,   g_x2);
    cudaGetSymbolAddress((void**)&p_h,    g_h);
    cudaGetSymbolAddress((void**)&p_wqkv, g_wqkv);
    cudaGetSymbolAddress((void**)&p_wo,   g_wo);
    cudaGetSymbolAddress((void**)&p_fc1,  g_fc1);
    cudaGetSymbolAddress((void**)&p_fc2,  g_fc2);

    cudaFuncSetAttribute(halo_attn_mma,
                         cudaFuncAttributeMaxDynamicSharedMemorySize, SMEM_ATTN);
    cudaFuncSetAttribute(mgemm<1>, cudaFuncAttributeMaxDynamicSharedMemorySize, GEMM_SMEM + 1024);
    cudaFuncSetAttribute(mgemm<2>, cudaFuncAttributeMaxDynamicSharedMemorySize, GEMM_SMEM + 1024);
    cudaFuncSetAttribute(mgemm<3>, cudaFuncAttributeMaxDynamicSharedMemorySize, GEMM_SMEM + 1024);
    cudaFuncSetAttribute(mgemm<4>, cudaFuncAttributeMaxDynamicSharedMemorySize, GEMM_SMEM + 1024);

    // 1) weights -> bf16 (q scale folded)
    prep_w<<<1024, 256>>>(wq, wkv, wo, fc1w, fc2w);
    // 2) LN1 + NHWC transpose (bf16 ln out + fp32 raw copy)
    ln1_kernel<<<PIX/32, 256>>>(x, ln1w, ln1b);
    // 3) QKV: (50176,256)x(768,256)^T -> bf16
    mgemm<4><<<dim3(6, 392), 256, GEMM_SMEM + 1024>>>(p_xln, p_wqkv, nullptr, p_qkvb, 768, 256,
                                           nullptr, nullptr, nullptr, nullptr);
    // 4) MMA halo attention -> bf16
    halo_attn_mma<<<NWIN*HEADS, 128, SMEM_ATTN>>>(relh, relw, p_qkvb, p_attn);
    // 5) out proj + residual: x1 = x + gamma1*(attn@wo^T + bo)
    mgemm<1><<<dim3(2, 392), 256, GEMM_SMEM + 1024>>>(p_attn, p_wo, p_x1, nullptr, 256, 256,
                                           bo, p_xn, gamma1, nullptr);
    // 6) LN2 -> bf16
    ln2_kernel<<<PIX/8, 256>>>(p_x1, ln2w, ln2b, p_x2);
    // 7) fc1 + gelu -> bf16
    mgemm<2><<<dim3(8, 392), 256, GEMM_SMEM + 1024>>>(p_x2, p_fc1, nullptr, p_h, 1024, 256,
                                           fc1b, nullptr, nullptr, nullptr);
    // 8) fc2 + gamma2 residual + NHWC->NCHW into d_out
    mgemm<3><<<dim3(2, 392), 256, GEMM_SMEM + 1024>>>(p_h, p_fc2, nullptr, nullptr, 256, 1024,
                                           fc2b, p_x1, gamma2, out);
}

// round 9
// speedup vs baseline: 1.0618x; 1.0154x over previous
#include <cuda_runtime.h>
#include <cuda_bf16.h>
#include <math.h>
#include <stdint.h>

// ---------------- problem constants ----------------
#define BB    16
#define CCH   256
#define HH    56
#define WW    56
#define HWSZ  (HH*WW)            // 3136
#define PIX   (BB*HWSZ)          // 50176
#define HEADS 8
#define DHEAD 32
#define BLOCK 7
#define HALO  3
#define WIN   13
#define NWIN  1024
#define HIDDEN 1024

// ---------------- scratch (device globals) ----------------
__device__ float          g_xn  [(size_t)PIX*256];
__device__ __nv_bfloat16  g_xln [(size_t)PIX*256];
__device__ __nv_bfloat16  g_qkvb[(size_t)PIX*768];
__device__ __nv_bfloat16  g_attn[(size_t)PIX*256];
__device__ float          g_x1  [(size_t)PIX*256];
__device__ __nv_bfloat16  g_x2  [(size_t)PIX*256];
__device__ __nv_bfloat16  g_h   [(size_t)PIX*1024];
__device__ __nv_bfloat16  g_wqkv[768*256];
__device__ __nv_bfloat16  g_wo  [256*256];
__device__ __nv_bfloat16  g_fc1 [1024*256];
__device__ __nv_bfloat16  g_fc2 [256*1024];

// ---------------- helpers ----------------
__device__ __forceinline__ uint32_t s2u(const void* p) {
    return (uint32_t)__cvta_generic_to_shared(p);
}
#define SWZ(x) ((x) ^ (((x) >> 3) & 0x70))

__device__ __forceinline__ unsigned pack_bf2(float a, float b) {
    __nv_bfloat162 t = __floats2bfloat162_rn(a, b);
    return *reinterpret_cast<unsigned*>(&t);
}

#define CPA(dst, src) \
    asm volatile("cp.async.cg.shared.global [%0], [%1], 16;" \
                 :: "r"(dst), "l"(src) : "memory")

__device__ __forceinline__ void ldm4(uint32_t* r, uint32_t addr) {
    asm volatile("ldmatrix.sync.aligned.m8n8.x4.shared.b16 {%0,%1,%2,%3}, [%4];"
        : "=r"(r[0]), "=r"(r[1]), "=r"(r[2]), "=r"(r[3]) : "r"(addr));
}
__device__ __forceinline__ void ldm4t(uint32_t* r, uint32_t addr) {
    asm volatile("ldmatrix.sync.aligned.m8n8.x4.trans.shared.b16 {%0,%1,%2,%3}, [%4];"
        : "=r"(r[0]), "=r"(r[1]), "=r"(r[2]), "=r"(r[3]) : "r"(addr));
}
__device__ __forceinline__ void mma16816(float* c, const uint32_t* a,
                                         const uint32_t* b) {
    asm volatile(
        "mma.sync.aligned.m16n8k16.row.col.f32.bf16.bf16.f32 "
        "{%0,%1,%2,%3}, {%4,%5,%6,%7}, {%8,%9}, {%0,%1,%2,%3};"
        : "+f"(c[0]), "+f"(c[1]), "+f"(c[2]), "+f"(c[3])
        : "r"(a[0]), "r"(a[1]), "r"(a[2]), "r"(a[3]), "r"(b[0]), "r"(b[1]));
}

// ---------------- weight conversion to bf16 (q scale folded into wq) ----------------
__global__ void prep_w(const float* __restrict__ wq, const float* __restrict__ wkv,
                       const float* __restrict__ wo, const float* __restrict__ fc1w,
                       const float* __restrict__ fc2w)
{
    int i = blockIdx.x * 256 + threadIdx.x;      // 0..262143
    if (i < 65536) {
        g_wqkv[i] = __float2bfloat16(wq[i] * 0.17677669529663687f);
        g_wo[i]   = __float2bfloat16(wo[i]);
    }
    if (i < 131072) g_wqkv[65536 + i] = __float2bfloat16(wkv[i]);
    g_fc1[i] = __float2bfloat16(fc1w[i]);
    g_fc2[i] = __float2bfloat16(fc2w[i]);
}

// ---------------- LN1: NCHW -> NHWC (bf16 ln output + fp32 raw copy) ----------------
__global__ void __launch_bounds__(256)
ln1_kernel(const float* __restrict__ x, const float* __restrict__ w,
           const float* __restrict__ bch)
{
    __shared__ float sm[256][33];
    __shared__ float smu[32], srs[32];
    const int t = threadIdx.x;
    const int pixbase = blockIdx.x * 32;
    const int b   = pixbase / HWSZ;
    const int hw0 = pixbase % HWSZ;
    const float* xb = x + (size_t)b*CCH*HWSZ + hw0;
    const int lane = t & 31, grp = t >> 5;

    #pragma unroll
    for (int i = 0; i < 32; i++) {
        int c = i*8 + grp;
        sm[c][lane] = xb[(size_t)c*HWSZ + lane];
    }
    __syncthreads();

    #pragma unroll
    for (int pi = 0; pi < 4; pi++) {
        int px = grp*4 + pi;
        float s = 0.f, s2 = 0.f;
        #pragma unroll
        for (int j = 0; j < 8; j++) {
            float v = sm[lane + j*32][px];
            s += v; s2 += v*v;
        }
        #pragma unroll
        for (int o = 16; o; o >>= 1) {
            s  += __shfl_xor_sync(~0u, s,  o);
            s2 += __shfl_xor_sync(~0u, s2, o);
        }
        if (lane == 0) {
            float mu = s * (1.f/256.f);
            smu[px] = mu;
            srs[px] = rsqrtf(s2*(1.f/256.f) - mu*mu + 1e-6f);
        }
    }
    __syncthreads();

    const float wgt = w[t], bia = bch[t];
    #pragma unroll
    for (int i = 0; i < 32; i++) {
        float v = sm[t][i];
        size_t row = (size_t)(pixbase + i) * 256;
        g_xn [row + t] = v;
        g_xln[row + t] = __float2bfloat16((v - smu[i]) * srs[i] * wgt + bia);
    }
}

// ---------------- LN2: NHWC rows, fp32 in -> bf16 out ----------------
__global__ void __launch_bounds__(256)
ln2_kernel(const float* __restrict__ x1, const float* __restrict__ w,
           const float* __restrict__ bch, __nv_bfloat16* __restrict__ x2)
{
    int gw = (blockIdx.x * blockDim.x + threadIdx.x) >> 5;
    int lane = threadIdx.x & 31;
    if (gw >= PIX) return;
    const float4* r = (const float4*)(x1 + (size_t)gw*256);
    float4 a = r[lane], c = r[lane + 32];
    float s  = a.x+a.y+a.z+a.w + c.x+c.y+c.z+c.w;
    float s2 = a.x*a.x+a.y*a.y+a.z*a.z+a.w*a.w
             + c.x*c.x+c.y*c.y+c.z*c.z+c.w*c.w;
    #pragma unroll
    for (int o = 16; o; o >>= 1) {
        s  += __shfl_xor_sync(~0u, s,  o);
        s2 += __shfl_xor_sync(~0u, s2, o);
    }
    float mu   = s * (1.f/256.f);
    float rstd = rsqrtf(s2*(1.f/256.f) - mu*mu + 1e-6f);
    const float4* w4 = (const float4*)w;
    const float4* b4 = (const float4*)bch;
    float4 wa = w4[lane], ba = b4[lane];
    float4 wc = w4[lane+32], bc = b4[lane+32];
    uint2* o2 = (uint2*)(x2 + (size_t)gw*256);
    uint2 ua, uc;
    ua.x = pack_bf2((a.x-mu)*rstd*wa.x + ba.x, (a.y-mu)*rstd*wa.y + ba.y);
    ua.y = pack_bf2((a.z-mu)*rstd*wa.z + ba.z, (a.w-mu)*rstd*wa.w + ba.w);
    uc.x = pack_bf2((c.x-mu)*rstd*wc.x + bc.x, (c.y-mu)*rstd*wc.y + bc.y);
    uc.y = pack_bf2((c.z-mu)*rstd*wc.z + bc.z, (c.w-mu)*rstd*wc.w + bc.w);
    o2[lane] = ua;
    o2[lane + 32] = uc;
}

// ---------------- MMA halo attention: one CTA (128 thr) per (window, head) ----------
// Q padded 49->64 rows, keys padded 169->176 processed in halves 96+80 (register
// diet). Bias tables bf16 stride-18-halfword (conflict-free), no-max softmax.
// smem 45192 B, target 5 CTAs/SM.
#define Q_OFF   0
#define K_OFF   5120
#define V_OFF   19200
#define QH_OFF  33280
#define QW_OFF  35584
#define SRH_OFF 37888
#define SRW_OFF 41188
#define JB_OFF  44488
#define SMEM_ATTN 45192
__global__ void __launch_bounds__(128, 5)
halo_attn_mma(const float* __restrict__ relh, const float* __restrict__ relw,
              const __nv_bfloat16* __restrict__ qkv, __nv_bfloat16* __restrict__ attn)
{
    extern __shared__ char sm[];
    const uint32_t smu = s2u(sm);
    float* srh   = (float*)(sm + SRH_OFF);  // 25 x 33 fp32
    float* srw   = (float*)(sm + SRW_OFF);  // 25 x 33 fp32
    int*   jbase = (int*)  (sm + JB_OFF);   // 176

    const int tid  = threadIdx.x;
    const int head = blockIdx.x & 7;
    const int win  = blockIdx.x >> 3;
    const int b    = win >> 6, blk = win & 63;
    const int rowbase = (blk >> 3) * BLOCK, colbase = (blk & 7) * BLOCK;
    const int pb = b * HWSZ;
    const int hc = head * DHEAD;

    // ---- phase 0: rel tables, jbase, Q fill (uint4), bias defaults ----
    for (int i = tid; i < 800; i += 128) {
        int r = i >> 5, d = i & 31;
        srh[r*33 + d] = relh[i];
        srw[r*33 + d] = relw[i];
    }
    for (int j = tid; j < 176; j += 128) {
        int ki = (j * 1261) >> 14, kj = j - 13*ki;
        int gr = rowbase + ki - HALO, gc = colbase + kj - HALO;
        bool ok = (j < 169) && gr >= 0 && gr < HH && gc >= 0 && gc < WW;
        jbase[j] = ok ? ((pb + gr*WW + gc)*768 + hc) : -1;
    }
    for (int i = tid; i < 256; i += 128) {          // Q: 64 rows x 4 uint4
        int qi = i >> 2, seg = i & 3;
        uint4 v = make_uint4(0, 0, 0, 0);
        if (qi < 49) {
            int x = qi / 7, y = qi - 7*x;
            int p = pb + (rowbase + x)*WW + colbase + y;
            v = *(const uint4*)(qkv + (size_t)p*768 + hc + seg*8);
        }
        *(uint4*)(sm + Q_OFF + qi*80 + seg*16) = v;
    }
    for (int i = tid; i < 288; i += 128) {          // qh2/qw2 bf16 default -3.39e38
        ((uint4*)(sm + QH_OFF))[i] =
            make_uint4(0xFF7FFF7Fu, 0xFF7FFF7Fu, 0xFF7FFF7Fu, 0xFF7FFF7Fu);
    }
    __syncthreads();

    // ---- phase 1: K/V fill + bias tables (bf16, stride 18 halfwords) ----
    for (int i = tid; i < 704; i += 128) {          // 176 rows x 4 uint4
        int j = i >> 2, seg = i & 3;
        int base = jbase[j];
        uint4 kv = make_uint4(0, 0, 0, 0), vv = make_uint4(0, 0, 0, 0);
        if (base >= 0) {
            kv = *(const uint4*)(qkv + base + 256 + seg*8);
            vv = *(const uint4*)(qkv + base + 512 + seg*8);
        }
        *(uint4*)(sm + K_OFF + j*80 + seg*16) = kv;
        *(uint4*)(sm + V_OFF + j*80 + seg*16) = vv;
    }
    for (int e = tid; e < 49*14; e += 128) {        // qh2[qi][ki]
        int qi = e / 14, r = e % 14;
        int x = qi / 7;
        int gr = rowbase + r - HALO;
        if (r < 13 && gr >= 0 && gr < HH) {
            const uint32_t* q = (const uint32_t*)(sm + Q_OFF + qi*80);
            const float* rl = srh + (r + 12 - x)*33;
            float acc = 0.f;
            #pragma unroll
            for (int d2 = 0; d2 < 16; d2++) {
                __nv_bfloat162 qq = *(const __nv_bfloat162*)&q[d2];
                acc += __bfloat162float(qq.x)*rl[d2*2] +
                       __bfloat162float(qq.y)*rl[d2*2+1];
            }
            *(__nv_bfloat16*)(sm + QH_OFF + (qi*18 + r)*2) = __float2bfloat16(acc);
        }
    }
    for (int e = tid; e < 49*13; e += 128) {        // qw2[qi][kj]
        int qi = e / 13, r = e % 13;
        int y = qi % 7;
        int gc = colbase + r - HALO;
        if (gc >= 0 && gc < WW) {
            const uint32_t* q = (const uint32_t*)(sm + Q_OFF + qi*80);
            const float* rl = srw + (r + 12 - y)*33;
            float acc = 0.f;
            #pragma unroll
            for (int d2 = 0; d2 < 16; d2++) {
                __nv_bfloat162 qq = *(const __nv_bfloat162*)&q[d2];
                acc += __bfloat162float(qq.x)*rl[d2*2] +
                       __bfloat162float(qq.y)*rl[d2*2+1];
            }
            *(__nv_bfloat16*)(sm + QW_OFF + (qi*18 + r)*2) = __float2bfloat16(acc);
        }
    }
    __syncthreads();

    const int lane = tid & 31, wm = tid >> 5;
    const int qiA = wm*16 + (lane >> 2);

    // A frags (Q) once for both halves
    const uint32_t a_addr = smu + Q_OFF + (wm*16 + (lane & 15))*80 + ((lane >> 4)*8)*2;
    uint32_t a0[4], a1[4];
    ldm4(a0, a_addr);
    ldm4(a1, a_addr + 32);

    const uint32_t b_row   = (lane & 7) + ((lane & 16) >> 1);
    const uint32_t b_col16 = ((lane >> 3) & 1) * 16;
    const uint32_t v_rowoff = (lane & 15);
    const uint32_t v_coloff = ((lane >> 4) * 8) * 2;

    float o[4][4];
    #pragma unroll
    for (int nt = 0; nt < 4; nt++)
        #pragma unroll
        for (int e = 0; e < 4; e++) o[nt][e] = 0.f;
    float sA = 0.f, sB = 0.f;

    #pragma unroll
    for (int jh = 0; jh < 2; jh++) {
        const int NG = jh ? 5 : 6;        // 16-key groups this half
        const int j0 = jh ? 96 : 0;

        // ---- QK^T for this key half ----
        float c[12][4];
        #pragma unroll
        for (int nt = 0; nt < 12; nt++)
            #pragma unroll
            for (int e = 0; e < 4; e++) c[nt][e] = 0.f;

        #pragma unroll
        for (int kt = 0; kt < 2; kt++) {
            const uint32_t* a = kt ? a1 : a0;
            #pragma unroll
            for (int g = 0; g < 6; g++) {
                if (g < NG) {
                    uint32_t bfr[4];
                    ldm4(bfr, smu + K_OFF + (j0 + g*16 + b_row)*80 + kt*32 + b_col16);
                    mma16816(c[2*g],     a, bfr);
                    mma16816(c[2*g + 1], a, bfr + 2);
                }
            }
        }

        // ---- bias + mask + no-max exp (incremental ki/kj) ----
        {
            int jE = j0 + (lane & 3)*2;
            int ki = (jE * 1261) >> 14, kj = jE - 13*ki;
            #pragma unroll
            for (int nt = 0; nt < 12; nt++) {
                if (nt < 2*NG) {
                    int ki1 = ki, kj1 = kj + 1;
                    if (kj1 == 13) { kj1 = 0; ki1++; }
                    float h0A = __bfloat162float(*(const __nv_bfloat16*)(sm + QH_OFF + (qiA*18 + ki)*2));
                    float w0A = __bfloat162float(*(const __nv_bfloat16*)(sm + QW_OFF + (qiA*18 + kj)*2));
                    float h1A = __bfloat162float(*(const __nv_bfloat16*)(sm + QH_OFF + (qiA*18 + ki1)*2));
                    float w1A = __bfloat162float(*(const __nv_bfloat16*)(sm + QW_OFF + (qiA*18 + kj1)*2));
                    float h0B = __bfloat162float(*(const __nv_bfloat16*)(sm + QH_OFF + ((qiA+8)*18 + ki)*2));
                    float w0B = __bfloat162float(*(const __nv_bfloat16*)(sm + QW_OFF + ((qiA+8)*18 + kj)*2));
                    float h1B = __bfloat162float(*(const __nv_bfloat16*)(sm + QH_OFF + ((qiA+8)*18 + ki1)*2));
                    float w1B = __bfloat162float(*(const __nv_bfloat16*)(sm + QW_OFF + ((qiA+8)*18 + kj1)*2));
                    c[nt][0] = __expf(c[nt][0] + h0A + w0A); sA += c[nt][0];
                    c[nt][1] = __expf(c[nt][1] + h1A + w1A); sA += c[nt][1];
                    c[nt][2] = __expf(c[nt][2] + h0B + w0B); sB += c[nt][2];
                    c[nt][3] = __expf(c[nt][3] + h1B + w1B); sB += c[nt][3];
                    kj += 8;
                    if (kj >= 13) { kj -= 13; ki++; }
                }
            }
        }

        // ---- P @ V for this half ----
        #pragma unroll
        for (int kt2 = 0; kt2 < 6; kt2++) {
            if (kt2 < NG) {
                uint32_t pa[4];
                pa[0] = pack_bf2(c[2*kt2][0],     c[2*kt2][1]);
                pa[1] = pack_bf2(c[2*kt2][2],     c[2*kt2][3]);
                pa[2] = pack_bf2(c[2*kt2 + 1][0], c[2*kt2 + 1][1]);
                pa[3] = pack_bf2(c[2*kt2 + 1][2], c[2*kt2 + 1][3]);
                const uint32_t vbase = smu + V_OFF + (j0 + kt2*16 + v_rowoff)*80 + v_coloff;
                uint32_t vb[4];
                ldm4t(vb, vbase);
                mma16816(o[0], pa, vb);
                mma16816(o[1], pa, vb + 2);
                ldm4t(vb, vbase + 32);
                mma16816(o[2], pa, vb);
                mma16816(o[3], pa, vb + 2);
            }
        }
    }

    // ---- softmax denominators (quad reduce) ----
    sA += __shfl_xor_sync(~0u, sA, 1); sA += __shfl_xor_sync(~0u, sA, 2);
    sB += __shfl_xor_sync(~0u, sB, 1); sB += __shfl_xor_sync(~0u, sB, 2);
    const float invA = 1.f / sA, invB = 1.f / sB;

    // ---- store (only valid query rows) ----
    #pragma unroll
    for (int half = 0; half < 2; half++) {
        int qi = qiA + half*8;
        if (qi < 49) {
            int x = qi / 7, y = qi - 7*x;
            int p = pb + (rowbase + x)*WW + colbase + y;
            __nv_bfloat16* dst = attn + (size_t)p*256 + hc + (lane & 3)*2;
            float inv = half ? invB : invA;
            #pragma unroll
            for (int nt = 0; nt < 4; nt++)
                *(uint32_t*)(dst + nt*8) =
                    pack_bf2(o[nt][half*2] * inv, o[nt][half*2 + 1] * inv);
        }
    }
}

// ---------------- bf16 mma.sync GEMM: C[M,N] = A[M,K] * W[N,K]^T ----------------
// CTA tile 128x128, warp tile 32x64, k-tile 64, cp.async 3-stage pipeline.
// MODE 0: fp32 store   MODE 1: x1 = resid + gamma*(acc+bias) fp32
// MODE 2: bf16 gelu    MODE 3: out_nchw = resid + gamma*(acc+bias)
// MODE 4: bf16 plain store
#define GEMM_SMEM (3*32768)
template<int MODE>
__global__ void __launch_bounds__(256)
mgemm(const __nv_bfloat16* __restrict__ A, const __nv_bfloat16* __restrict__ W,
      float* __restrict__ Cf, __nv_bfloat16* __restrict__ Cb, int N, int K,
      const float* __restrict__ bias, const float* __restrict__ resid,
      const float* __restrict__ gamma, float* __restrict__ out2)
{
    extern __shared__ char smraw[];
    uint32_t dynb  = s2u(smraw);
    const uint32_t tiles_u = (dynb + 1023) & ~1023u;

    const int tid  = threadIdx.x;
    const int lane = tid & 31, warp = tid >> 5;
    const int wm = warp & 3, wn = warp >> 2;
    const int mBase = blockIdx.y * 128;
    const int nBase = blockIdx.x * 128;
    const __nv_bfloat16* Abase = A + (size_t)mBase * K;
    const __nv_bfloat16* Wbase = W + (size_t)nBase * K;
    const int nkt = K >> 6;

    float c[2][8][4];
    #pragma unroll
    for (int mi = 0; mi < 2; mi++)
        #pragma unroll
        for (int ni = 0; ni < 8; ni++)
            #pragma unroll
            for (int j = 0; j < 4; j++) c[mi][ni][j] = 0.f;

    const int arow0    = wm*32 + (lane & 15);
    const int acolbase = (lane >> 4) * 16;
    const int brow0    = wn*64 + ((lane >> 4) << 3) + (lane & 7);
    const int bcolbase = ((lane >> 3) & 1) * 16;

    auto LOADT = [&](int kt) {
        const __nv_bfloat16* Ag = Abase + kt * 64;
        const __nv_bfloat16* Wg = Wbase + kt * 64;
        uint32_t sa = tiles_u + (kt % 3) * 32768;
        #pragma unroll
        for (int i = 0; i < 4; i++) {
            int idx = tid + i * 256;
            int row = idx >> 3, ch = idx & 7;
            uint32_t off = SWZ(row * 128 + ch * 16);
            CPA(sa + off,         Ag + (size_t)row * K + ch * 8);
            CPA(sa + 16384 + off, Wg + (size_t)row * K + ch * 8);
        }
        asm volatile("cp.async.commit_group;" ::: "memory");
    };

    LOADT(0);
    if (nkt > 1) LOADT(1);
    for (int kt = 0; kt < nkt; kt++) {
        if (kt + 1 < nkt) {
            asm volatile("cp.async.wait_group 1;" ::: "memory");
        } else {
            asm volatile("cp.async.wait_group 0;" ::: "memory");
        }
        __syncthreads();
        if (kt + 2 < nkt) LOADT(kt + 2);

        const uint32_t sa = tiles_u + (kt % 3) * 32768;
        const uint32_t sb = sa + 16384;
        #pragma unroll
        for (int kk = 0; kk < 4; kk++) {
            uint32_t af[2][4];
            ldm4(af[0], sa + SWZ(arow0 * 128 + kk*32 + acolbase));
            ldm4(af[1], sa + SWZ((arow0 + 16) * 128 + kk*32 + acolbase));
            uint32_t bf_[4][4];
            #pragma unroll
            for (int nj = 0; nj < 4; nj++)
                ldm4(bf_[nj], sb + SWZ((brow0 + nj*16) * 128 + kk*32 + bcolbase));
            #pragma unroll
            for (int mi = 0; mi < 2; mi++)
                #pragma unroll
                for (int ni = 0; ni < 8; ni++)
                    mma16816(c[mi][ni], af[mi], &bf_[ni >> 1][(ni & 1) * 2]);
        }
    }

    // ---------------- epilogue ----------------
    const int colq = (lane & 3) * 2;
    const int rowq = lane >> 2;

    #pragma unroll
    for (int ni = 0; ni < 8; ni++) {
        const int col = nBase + wn*64 + ni*8 + colq;
        float2 bb = make_float2(0.f, 0.f), gg = make_float2(0.f, 0.f);
        if (MODE == 1 || MODE == 2 || MODE == 3) bb = *(const float2*)(bias + col);
        if (MODE == 1 || MODE == 3) gg = *(const float2*)(gamma + col);
        #pragma unroll
        for (int mi = 0; mi < 2; mi++) {
            #pragma unroll
            for (int h = 0; h < 2; h++) {
                const int row = mBase + wm*32 + mi*16 + h*8 + rowq;
                const float v0 = c[mi][ni][h*2], v1 = c[mi][ni][h*2+1];
                if (MODE == 0) {
                    *(float2*)(Cf + (size_t)row * N + col) = make_float2(v0, v1);
                } else if (MODE == 1) {
                    float2 r2 = *(const float2*)(resid + (size_t)row * 256 + col);
                    *(float2*)(Cf + (size_t)row * 256 + col) =
                        make_float2(r2.x + gg.x * (v0 + bb.x),
                                    r2.y + gg.y * (v1 + bb.y));
                } else if (MODE == 2) {
                    float t0 = v0 + bb.x, t1 = v1 + bb.y;
                    float e0 = 0.5f * t0 * (1.f + erff(t0 * 0.70710678118654752f));
                    float e1 = 0.5f * t1 * (1.f + erff(t1 * 0.70710678118654752f));
                    *(unsigned*)(Cb + (size_t)row * N + col) = pack_bf2(e0, e1);
                } else if (MODE == 3) {
                    const int bimg = row / HWSZ;
                    const int hw   = row - bimg * HWSZ;
                    const float* rp = resid + (size_t)row * 256 + col;
                    float* ob = out2 + (size_t)(bimg * 256 + col) * HWSZ + hw;
                    ob[0]    = rp[0] + gg.x * (v0 + bb.x);
                    ob[HWSZ] = rp[1] + gg.y * (v1 + bb.y);
                } else {
                    *(unsigned*)(Cb + (size_t)row * N + col) = pack_bf2(v0, v1);
                }
            }
        }
    }
}

// ---------------- launcher ----------------
extern "C" void kernel_launch(void* const* d_in, const int* in_sizes, int n_in,
                              void* d_out, int out_size)
{
    const float* x      = (const float*)d_in[0];
    const float* ln1w   = (const float*)d_in[1];
    const float* ln1b   = (const float*)d_in[2];
    const float* ln2w   = (const float*)d_in[3];
    const float* ln2b   = (const float*)d_in[4];
    const float* wq     = (const float*)d_in[5];
    const float* wkv    = (const float*)d_in[6];
    const float* wo     = (const float*)d_in[7];
    const float* bo     = (const float*)d_in[8];
    const float* relh   = (const float*)d_in[9];
    const float* relw   = (const float*)d_in[10];
    const float* gamma1 = (const float*)d_in[11];
    const float* gamma2 = (const float*)d_in[12];
    const float* fc1w   = (const float*)d_in[13];
    const float* fc1b   = (const float*)d_in[14];
    const float* fc2w   = (const float*)d_in[15];
    const float* fc2b   = (const float*)d_in[16];
    float* out = (float*)d_out;

    float *p_xn, *p_x1;
    __nv_bfloat16 *p_xln, *p_qkvb, *p_attn, *p_x2, *p_h, *p_wqkv, *p_wo, *p_fc1, *p_fc2;
    cudaGetSymbolAddress((void**)&p_xn,   g_xn);
    cudaGetSymbolAddress((void**)&p_xln,  g_xln);
    cudaGetSymbolAddress((void**)&p_qkvb, g_qkvb);
    cudaGetSymbolAddress((void**)&p_attn, g_attn);
    cudaGetSymbolAddress((void**)&p_x1,   g_x1);
    cudaGetSymbolAddress((void**)&p_x2,   g_x2);
    cudaGetSymbolAddress((void**)&p_h,    g_h);
    cudaGetSymbolAddress((void**)&p_wqkv, g_wqkv);
    cudaGetSymbolAddress((void**)&p_wo,   g_wo);
    cudaGetSymbolAddress((void**)&p_fc1,  g_fc1);
    cudaGetSymbolAddress((void**)&p_fc2,  g_fc2);

    cudaFuncSetAttribute(halo_attn_mma,
                         cudaFuncAttributeMaxDynamicSharedMemorySize, SMEM_ATTN);
    cudaFuncSetAttribute(mgemm<1>, cudaFuncAttributeMaxDynamicSharedMemorySize, GEMM_SMEM + 1024);
    cudaFuncSetAttribute(mgemm<2>, cudaFuncAttributeMaxDynamicSharedMemorySize, GEMM_SMEM + 1024);
    cudaFuncSetAttribute(mgemm<3>, cudaFuncAttributeMaxDynamicSharedMemorySize, GEMM_SMEM + 1024);
    cudaFuncSetAttribute(mgemm<4>, cudaFuncAttributeMaxDynamicSharedMemorySize, GEMM_SMEM + 1024);

    // 1) weights -> bf16 (q scale folded)
    prep_w<<<1024, 256>>>(wq, wkv, wo, fc1w, fc2w);
    // 2) LN1 + NHWC transpose (bf16 ln out + fp32 raw copy)
    ln1_kernel<<<PIX/32, 256>>>(x, ln1w, ln1b);
    // 3) QKV: (50176,256)x(768,256)^T -> bf16
    mgemm<4><<<dim3(6, 392), 256, GEMM_SMEM + 1024>>>(p_xln, p_wqkv, nullptr, p_qkvb, 768, 256,
                                           nullptr, nullptr, nullptr, nullptr);
    // 4) MMA halo attention -> bf16
    halo_attn_mma<<<NWIN*HEADS, 128, SMEM_ATTN>>>(relh, relw, p_qkvb, p_attn);
    // 5) out proj + residual: x1 = x + gamma1*(attn@wo^T + bo)
    mgemm<1><<<dim3(2, 392), 256, GEMM_SMEM + 1024>>>(p_attn, p_wo, p_x1, nullptr, 256, 256,
                                           bo, p_xn, gamma1, nullptr);
    // 6) LN2 -> bf16
    ln2_kernel<<<PIX/8, 256>>>(p_x1, ln2w, ln2b, p_x2);
    // 7) fc1 + gelu -> bf16
    mgemm<2><<<dim3(8, 392), 256, GEMM_SMEM + 1024>>>(p_x2, p_fc1, nullptr, p_h, 1024, 256,
                                           fc1b, nullptr, nullptr, nullptr);
    // 8) fc2 + gamma2 residual + NHWC->NCHW into d_out
    mgemm<3><<<dim3(2, 392), 256, GEMM_SMEM + 1024>>>(p_h, p_fc2, nullptr, nullptr, 256, 1024,
                                           fc2b, p_x1, gamma2, out);
}